// round 5
// baseline (speedup 1.0000x reference)
#include <cuda_runtime.h>
#include <math.h>

#define FULLMASK 0xffffffffu

#define Bc 8
#define Tc 24
#define Nc 1000
#define Ec 1000
#define F_INc 16
#define C_RAWc 8
#define DMc 32
#define HCc 32
#define PREDc 12
#define LAMc 0.3f
#define EPSc 1e-8f
#define MAXD 64
#define ESTRIDE 24     // padded edge member list stride (int4-aligned)
#define USH 15         // g_u slice shift: 1024 rows * 32 floats
#define LRPP 4         // rows per warp-pair in k_lstm2

typedef unsigned long long u64;

// ---------------- scratch (device globals; no allocation) ----------------
__device__ int   g_edge_nodes[Ec * ESTRIDE];
__device__ int   g_edge_cnt[Ec];
__device__ int   g_node_edges[Nc * MAXD];
__device__ int   g_node_deg[Nc];
__device__ float g_feat[Bc * Nc * 16];
__device__ float g_msum[Bc * Ec];
__device__ float g_Wd[Bc * Ec];
__device__ float g_dvi[Bc * Nc];
__device__ float g_u[(size_t)Bc * Tc * 1024 * DMc];   // edge features, 1024-row slices
__device__ float g_hc[(size_t)Bc * Nc * Tc * HCc];    // conv outputs (LSTM inputs)

// ---------------- math helpers ----------------
__device__ __forceinline__ float sigmf(float x) { return __fdividef(1.f, 1.f + __expf(-x)); }
__device__ __forceinline__ float tanhf_(float x) { return 2.f * sigmf(2.f * x) - 1.f; }
__device__ __forceinline__ float siluf(float x) { return x * sigmf(x); }

// ---------------- adjacency build ----------------
__global__ void k_zero_deg() {
    int i = blockIdx.x * blockDim.x + threadIdx.x;
    if (i < Nc) g_node_deg[i] = 0;
}

__global__ void k_build_edges(const int* __restrict__ members,
                              const int* __restrict__ centers,
                              const int* __restrict__ offsets) {
    int e = blockIdx.x * blockDim.x + threadIdx.x;
    if (e >= Ec) return;
    int s = offsets[e], t = offsets[e + 1];
    int list[ESTRIDE];
    int cnt = 0;
    for (int m = s; m < t && cnt < ESTRIDE; m++) {
        int n = members[m];
        bool dup = false;
        for (int k = 0; k < cnt; k++) if (list[k] == n) { dup = true; break; }
        if (!dup) list[cnt++] = n;
    }
    {
        int c = centers[e];
        bool dup = false;
        for (int k = 0; k < cnt; k++) if (list[k] == c) { dup = true; break; }
        if (!dup && cnt < ESTRIDE) list[cnt++] = c;
    }
    g_edge_cnt[e] = cnt;
    for (int k = 0; k < cnt; k++) {
        int n = list[k];
        g_edge_nodes[e * ESTRIDE + k] = n;
        int pos = atomicAdd(&g_node_deg[n], 1);
        if (pos < MAXD) g_node_edges[n * MAXD + pos] = e;
    }
    for (int k = cnt; k < ESTRIDE; k++) g_edge_nodes[e * ESTRIDE + k] = Nc;  // dummy zero row in xs
}

__global__ void k_sort_nodes() {
    int n = blockIdx.x * blockDim.x + threadIdx.x;
    if (n >= Nc) return;
    int d = g_node_deg[n];
    if (d > MAXD) d = MAXD;
    g_node_deg[n] = d;
    int* L = g_node_edges + n * MAXD;
    for (int i = 1; i < d; i++) {
        int key = L[i];
        int j = i - 1;
        while (j >= 0 && L[j] > key) { L[j + 1] = L[j]; j--; }
        L[j + 1] = key;
    }
    int d8 = (d + 7) & ~7;
    if (d8 > MAXD) d8 = MAXD;
    for (int i = d; i < d8; i++) L[i] = Ec;  // dummy: g_u row 1000 is zeroed
}

// ---------------- dynamic features: mean/std over T ----------------
__global__ void k_feat(const float* __restrict__ xraw) {
    int idx = blockIdx.x * blockDim.x + threadIdx.x;
    if (idx >= Bc * Nc * C_RAWc) return;
    int c = idx % C_RAWc;
    int n = (idx / C_RAWc) % Nc;
    int b = idx / (C_RAWc * Nc);
    float s1 = 0.f, s2 = 0.f;
    #pragma unroll
    for (int t = 0; t < Tc; t++) {
        float v = xraw[((b * Tc + t) * Nc + n) * C_RAWc + c];
        s1 += v; s2 += v * v;
    }
    float mean = s1 * (1.f / Tc);
    float var = s2 * (1.f / Tc) - mean * mean;
    if (var < 0.f) var = 0.f;
    g_feat[(b * Nc + n) * 16 + c] = mean;
    g_feat[(b * Nc + n) * 16 + C_RAWc + c] = sqrtf(var);
}

// ---------------- per-edge mean similarity (warp per (b,e)) ----------------
__global__ void k_sim(const int* __restrict__ members,
                      const int* __restrict__ centers,
                      const int* __restrict__ offsets) {
    int gid = blockIdx.x * (blockDim.x >> 5) + (threadIdx.x >> 5);
    if (gid >= Bc * Ec) return;
    int e = gid % Ec;
    int b = gid / Ec;
    int lane = threadIdx.x & 31;
    int s = offsets[e];
    int cntm = offsets[e + 1] - s;
    int cn = centers[e];
    const float4* cf4 = (const float4*)(g_feat + (b * Nc + cn) * 16);
    float4 c0 = cf4[0], c1 = cf4[1], c2 = cf4[2], c3 = cf4[3];
    float cn2 = c0.x*c0.x + c0.y*c0.y + c0.z*c0.z + c0.w*c0.w
              + c1.x*c1.x + c1.y*c1.y + c1.z*c1.z + c1.w*c1.w
              + c2.x*c2.x + c2.y*c2.y + c2.z*c2.z + c2.w*c2.w
              + c3.x*c3.x + c3.y*c3.y + c3.z*c3.z + c3.w*c3.w;
    float cnorm = sqrtf(cn2);
    float acc = 0.f;
    for (int m = lane; m < cntm; m += 32) {
        int n = members[s + m];
        const float4* mf4 = (const float4*)(g_feat + (b * Nc + n) * 16);
        float4 m0 = mf4[0], m1 = mf4[1], m2 = mf4[2], m3 = mf4[3];
        float dot = m0.x*c0.x + m0.y*c0.y + m0.z*c0.z + m0.w*c0.w
                  + m1.x*c1.x + m1.y*c1.y + m1.z*c1.z + m1.w*c1.w
                  + m2.x*c2.x + m2.y*c2.y + m2.z*c2.z + m2.w*c2.w
                  + m3.x*c3.x + m3.y*c3.y + m3.z*c3.z + m3.w*c3.w;
        float mn2 = m0.x*m0.x + m0.y*m0.y + m0.z*m0.z + m0.w*m0.w
                  + m1.x*m1.x + m1.y*m1.y + m1.z*m1.z + m1.w*m1.w
                  + m2.x*m2.x + m2.y*m2.y + m2.z*m2.z + m2.w*m2.w
                  + m3.x*m3.x + m3.y*m3.y + m3.z*m3.z + m3.w*m3.w;
        float sim = dot / (sqrtf(mn2) * cnorm + EPSc);
        acc += fminf(fmaxf(sim, 0.f), 1.f);
    }
    #pragma unroll
    for (int o = 16; o > 0; o >>= 1) acc += __shfl_xor_sync(FULLMASK, acc, o);
    if (lane == 0) {
        float count = (float)cntm;
        if (count < 1.f) count = 1.f;
        g_msum[b * Ec + e] = acc / count;
    }
}

// ---------------- per-batch min-max normalize -> Wd ----------------
__global__ void k_wd(const float* __restrict__ W) {
    int b = blockIdx.x;
    int tid = threadIdx.x;
    __shared__ float rmn[256], rmx[256];
    float mn = 1e30f, mx = -1e30f;
    for (int e = tid; e < Ec; e += 256) {
        float v = g_msum[b * Ec + e];
        mn = fminf(mn, v); mx = fmaxf(mx, v);
    }
    rmn[tid] = mn; rmx[tid] = mx;
    __syncthreads();
    for (int s = 128; s > 0; s >>= 1) {
        if (tid < s) {
            rmn[tid] = fminf(rmn[tid], rmn[tid + s]);
            rmx[tid] = fmaxf(rmx[tid], rmx[tid + s]);
        }
        __syncthreads();
    }
    mn = rmn[0]; mx = rmx[0];
    float inv = __fdividef(1.f, mx - mn + EPSc);
    for (int e = tid; e < Ec; e += 256) {
        float v = (g_msum[b * Ec + e] - mn) * inv;
        g_Wd[b * Ec + e] = W[e] * (1.f + LAMc * v);
    }
}

// ---------------- node degree weights -> dvi (warp per (b,n)) ----------------
__global__ void k_dvi() {
    int gid = blockIdx.x * (blockDim.x >> 5) + (threadIdx.x >> 5);
    if (gid >= Bc * Nc) return;
    int n = gid % Nc;
    int b = gid / Nc;
    int lane = threadIdx.x & 31;
    int d = g_node_deg[n];
    float s = 0.f;
    for (int i = lane; i < d; i += 32)
        s += g_Wd[b * Ec + g_node_edges[n * MAXD + i]];
    #pragma unroll
    for (int o = 16; o > 0; o >>= 1) s += __shfl_xor_sync(FULLMASK, s, o);
    if (lane == 0) g_dvi[gid] = rsqrtf(fmaxf(s, EPSc));
}

// ---------------- edge gather (+ fused input projection) ----------------
__global__ __launch_bounds__(512) void k_edge_gather(const float* __restrict__ x,
                                                     const float* __restrict__ ipw,
                                                     const float* __restrict__ ipb) {
    extern __shared__ float xs[];            // (Nc+1)*32
    float* sipw = xs + (Nc + 1) * 32;        // 512
    float* sipb = sipw + 512;                // 32
    int bt = blockIdx.x >> 1;
    int part = blockIdx.x & 1;
    int b = bt / Tc;

    if (threadIdx.x < 512) sipw[threadIdx.x] = ipw[threadIdx.x];
    if (threadIdx.x < 32) sipb[threadIdx.x] = ipb[threadIdx.x];
    __syncthreads();

    const float* xb = x + (size_t)bt * Nc * F_INc;
    float4* xs4 = (float4*)xs;
    for (int i = threadIdx.x; i < (Nc + 1) * 8; i += 512) {
        int n = i >> 3, q = (i & 7) * 4;
        float4 v = make_float4(0.f, 0.f, 0.f, 0.f);
        if (n < Nc) {
            const float* xr = xb + n * F_INc;
            float a0 = sipb[q], a1 = sipb[q + 1], a2 = sipb[q + 2], a3 = sipb[q + 3];
            #pragma unroll
            for (int k = 0; k < F_INc; k++) {
                float xv = xr[k];
                a0 += xv * sipw[k * 32 + q];
                a1 += xv * sipw[k * 32 + q + 1];
                a2 += xv * sipw[k * 32 + q + 2];
                a3 += xv * sipw[k * 32 + q + 3];
            }
            float d = g_dvi[b * Nc + n];
            v = make_float4(a0 * d, a1 * d, a2 * d, a3 * d);
        }
        xs4[i] = v;
    }
    __syncthreads();

    int lane = threadIdx.x & 31;
    int w = threadIdx.x >> 5;
    float* ub = g_u + ((size_t)bt << USH);
    int e0 = part * (Ec / 2);
    for (int e = e0 + w; e < e0 + Ec / 2; e += 16) {
        int cnt = g_edge_cnt[e];
        const int4* ip = (const int4*)(g_edge_nodes + e * ESTRIDE);
        int4 v0 = ip[0], v1 = ip[1], v2 = ip[2], v3 = ip[3], v4 = ip[4], v5 = ip[5];
        int idx[ESTRIDE] = {v0.x, v0.y, v0.z, v0.w, v1.x, v1.y, v1.z, v1.w,
                            v2.x, v2.y, v2.z, v2.w, v3.x, v3.y, v3.z, v3.w,
                            v4.x, v4.y, v4.z, v4.w, v5.x, v5.y, v5.z, v5.w};
        float p0 = 0.f, p1 = 0.f, p2 = 0.f, p3 = 0.f;
        #pragma unroll
        for (int k = 0; k < ESTRIDE; k += 4) {
            p0 += xs[idx[k] * DMc + lane];
            p1 += xs[idx[k + 1] * DMc + lane];
            p2 += xs[idx[k + 2] * DMc + lane];
            p3 += xs[idx[k + 3] * DMc + lane];
        }
        float acc = (p0 + p1) + (p2 + p3);
        float sc = __fdividef(g_Wd[b * Ec + e], (float)cnt);
        ub[(e << 5) + lane] = acc * sc;
    }
    if (part) {  // zero pad rows 1000..1023 (dummy gather target)
        for (int e = Ec + w; e < 1024; e += 16) ub[(e << 5) + lane] = 0.f;
    }
}

// ---------------- node gather + conv + silu -> g_hc (warp per (b,n,t)) ----------------
__global__ __launch_bounds__(256) void k_hc(const float* __restrict__ cwg,
                                            const float* __restrict__ cbg) {
    int wid = threadIdx.x >> 5, lane = threadIdx.x & 31;
    int item = blockIdx.x * 8 + wid;       // Bc*Nc*Tc = 192000 items
    if (item >= Bc * Nc * Tc) return;
    int t = item % Tc;
    int rn = item / Tc;                    // b*Nc+n
    int n = rn % Nc;
    int b = rn / Nc;

    float cwr[32];
    #pragma unroll
    for (int f = 0; f < 32; f++) cwr[f] = cwg[f * 32 + lane];
    float cb = cbg[lane];

    int deg = g_node_deg[n];
    int d8 = (deg + 7) & ~7;
    float dvi = g_dvi[rn];
    const float* up = g_u + ((size_t)(b * Tc + t) << USH);
    const int* L = g_node_edges + n * MAXD;
    float p0 = 0.f, p1 = 0.f;
    for (int k = 0; k < d8; k += 8) {
        int4 a = *(const int4*)(L + k);
        int4 b2 = *(const int4*)(L + k + 4);
        p0 += up[(a.x << 5) + lane] + up[(a.z << 5) + lane]
            + up[(b2.x << 5) + lane] + up[(b2.z << 5) + lane];
        p1 += up[(a.y << 5) + lane] + up[(a.w << 5) + lane]
            + up[(b2.y << 5) + lane] + up[(b2.w << 5) + lane];
    }
    float acc = (p0 + p1) * dvi;
    float z = cb;
    #pragma unroll
    for (int f = 0; f < 32; f++)
        z += __shfl_sync(FULLMASK, acc, f) * cwr[f];
    g_hc[((size_t)rn * Tc + t) * 32 + lane] = siluf(z);
}

// ---------------- LSTM: register-resident weights, gate-split warp pairs ----------------
// block = 4 warps = 2 pairs, each pair handles LRPP rows; warp role 0: gates (i,f), role 1: (g,o).
__global__ __launch_bounds__(128) void k_lstm2(
    const float* __restrict__ wx, const float* __restrict__ wh,
    const float* __restrict__ lb,
    const float* __restrict__ hw1, const float* __restrict__ hb1,
    const float* __restrict__ hw2, const float* __restrict__ hb2,
    float* __restrict__ out, int Pout) {
    __shared__ float zbuf[2][2][2][2][LRPP][32];  // [pair][buf][role][z0/z1][r][lane]
    __shared__ float hw1S[1024], hb1S[32], hw2S[32 * PREDc], hb2S[PREDc];

    int tid = threadIdx.x, lane = tid & 31, wid = tid >> 5;
    int pair = wid >> 1, role = wid & 1;
    int rb = blockIdx.x * (2 * LRPP) + pair * LRPP;

    for (int i = tid; i < 1024; i += 128) hw1S[i] = hw1[i];
    for (int i = tid; i < 32 * PREDc; i += 128) hw2S[i] = hw2[i];
    if (tid < 32) hb1S[tid] = hb1[tid];
    if (tid < PREDc) hb2S[tid] = hb2[tid];

    int goff = role * 64;
    float w0[64], w1[64];
    #pragma unroll
    for (int i = 0; i < 32; i++) {
        w0[i] = wx[i * 128 + goff + lane];
        w1[i] = wx[i * 128 + goff + 32 + lane];
    }
    #pragma unroll
    for (int i = 0; i < 32; i++) {
        w0[32 + i] = wh[i * 128 + goff + lane];
        w1[32 + i] = wh[i * 128 + goff + 32 + lane];
    }
    float bz0 = lb[goff + lane], bz1 = lb[goff + 32 + lane];

    float hv[LRPP], cst[LRPP];
    #pragma unroll
    for (int r = 0; r < LRPP; r++) { hv[r] = 0.f; cst[r] = 0.f; }
    __syncthreads();

    for (int t = 0; t < Tc; t++) {
        float hcv[LRPP], z0[LRPP], z1[LRPP];
        #pragma unroll
        for (int r = 0; r < LRPP; r++) {
            hcv[r] = g_hc[((size_t)(rb + r) * Tc + t) * 32 + lane];
            z0[r] = bz0; z1[r] = bz1;
        }
        #pragma unroll
        for (int i = 0; i < 32; i++) {
            #pragma unroll
            for (int r = 0; r < LRPP; r++) {
                float a = __shfl_sync(FULLMASK, hcv[r], i);
                z0[r] += a * w0[i];
                z1[r] += a * w1[i];
            }
        }
        #pragma unroll
        for (int i = 0; i < 32; i++) {
            #pragma unroll
            for (int r = 0; r < LRPP; r++) {
                float a = __shfl_sync(FULLMASK, hv[r], i);
                z0[r] += a * w0[32 + i];
                z1[r] += a * w1[32 + i];
            }
        }
        int buf = t & 1;
        #pragma unroll
        for (int r = 0; r < LRPP; r++) {
            zbuf[pair][buf][role][0][r][lane] = z0[r];
            zbuf[pair][buf][role][1][r][lane] = z1[r];
        }
        __syncthreads();
        #pragma unroll
        for (int r = 0; r < LRPP; r++) {
            float oz0 = zbuf[pair][buf][role ^ 1][0][r][lane];
            float oz1 = zbuf[pair][buf][role ^ 1][1][r][lane];
            float zi = role ? oz0 : z0[r];
            float zf = role ? oz1 : z1[r];
            float zg = role ? z0[r] : oz0;
            float zo = role ? z1[r] : oz1;
            float ig = sigmf(zi);
            float fg = sigmf(zf);
            float gg = tanhf_(zg);
            float og = sigmf(zo);
            cst[r] = fg * cst[r] + ig * gg;
            hv[r] = og * tanhf_(cst[r]);
        }
    }

    // head (both roles compute identically; role 0 stores)
    #pragma unroll
    for (int r = 0; r < LRPP; r++) {
        int row = rb + r;
        int b = row / Nc;
        int n = row % Nc;
        float a = hb1S[lane];
        #pragma unroll 8
        for (int i = 0; i < 32; i++) {
            float hi = __shfl_sync(FULLMASK, hv[r], i);
            a += hi * hw1S[i * 32 + lane];
        }
        float y1 = siluf(a);
        float o = (lane < PREDc) ? hb2S[lane] : 0.f;
        #pragma unroll 8
        for (int j = 0; j < 32; j++) {
            float yj = __shfl_sync(FULLMASK, y1, j);
            if (lane < PREDc) o += yj * hw2S[j * PREDc + lane];
        }
        if (role == 0 && lane < Pout)
            out[((size_t)b * Pout + lane) * Nc + n] = o;
    }
}

// ---------------- launch ----------------
extern "C" void kernel_launch(void* const* d_in, const int* in_sizes, int n_in,
                              void* d_out, int out_size) {
    const float* x       = (const float*)d_in[0];
    const float* xraw    = (const float*)d_in[1];
    const float* W       = (const float*)d_in[3];
    const int*   members = (const int*)d_in[4];
    const int*   centers = (const int*)d_in[5];
    const int*   offsets = (const int*)d_in[6];
    const float* ipw     = (const float*)d_in[7];
    const float* ipb     = (const float*)d_in[8];
    const float* cw      = (const float*)d_in[9];
    const float* cb      = (const float*)d_in[10];
    const float* wx      = (const float*)d_in[11];
    const float* wh      = (const float*)d_in[12];
    const float* lb      = (const float*)d_in[13];
    const float* hw1     = (const float*)d_in[14];
    const float* hb1     = (const float*)d_in[15];
    const float* hw2     = (const float*)d_in[16];
    const float* hb2     = (const float*)d_in[17];
    float* out = (float*)d_out;
    int Pout = out_size / (Bc * Nc);

    int smem_edge = ((Nc + 1) * 32 + 512 + 32) * sizeof(float);  // 130304
    cudaFuncSetAttribute(k_edge_gather, cudaFuncAttributeMaxDynamicSharedMemorySize, smem_edge);

    k_zero_deg<<<4, 256>>>();
    k_build_edges<<<4, 256>>>(members, centers, offsets);
    k_sort_nodes<<<4, 256>>>();
    k_feat<<<(Bc * Nc * C_RAWc + 255) / 256, 256>>>(xraw);
    k_sim<<<(Bc * Ec + 7) / 8, 256>>>(members, centers, offsets);
    k_wd<<<Bc, 256>>>(W);
    k_dvi<<<(Bc * Nc + 7) / 8, 256>>>();
    k_edge_gather<<<Bc * Tc * 2, 512, smem_edge>>>(x, ipw, ipb);
    k_hc<<<(Bc * Nc * Tc + 7) / 8, 256>>>(cw, cb);
    k_lstm2<<<Bc * Nc / (2 * LRPP), 128>>>(wx, wh, lb, hw1, hb1, hw2, hb2, out, Pout);
}

// round 6
// speedup vs baseline: 1.3471x; 1.3471x over previous
#include <cuda_runtime.h>
#include <math.h>

#define FULLMASK 0xffffffffu

#define Bc 8
#define Tc 24
#define Nc 1000
#define Ec 1000
#define F_INc 16
#define C_RAWc 8
#define DMc 32
#define HCc 32
#define PREDc 12
#define LAMc 0.3f
#define EPSc 1e-8f
#define MAXD 64
#define ESTRIDE 24     // padded edge member list stride (int4-aligned)

typedef unsigned long long u64;

// ---------------- scratch (device globals; no allocation) ----------------
__device__ int   g_edge_nodes[Ec * ESTRIDE];
__device__ int   g_edge_cnt[Ec];
__device__ int   g_node_edges[Nc * MAXD];
__device__ int   g_node_deg[Nc];
__device__ float g_feat[Bc * Nc * 16];
__device__ float g_msum[Bc * Ec];
__device__ float g_Wd[Bc * Ec];
__device__ float g_dvi[Bc * Nc];
__device__ float g_ipwc[F_INc * DMc];   // folded ipw @ cw
__device__ float g_ipbc[DMc];           // folded ipb @ cw
__device__ float g_hc[(size_t)Bc * Nc * Tc * HCc];   // conv outputs (LSTM inputs)

// ---------------- math helpers ----------------
__device__ __forceinline__ float sigmf(float x) { return __fdividef(1.f, 1.f + __expf(-x)); }
__device__ __forceinline__ float tanhf_(float x) { return 2.f * sigmf(2.f * x) - 1.f; }
__device__ __forceinline__ float siluf(float x) { return x * sigmf(x); }

__device__ __forceinline__ u64 pack11(float x) {
    u64 r; asm("mov.b64 %0, {%1, %1};" : "=l"(r) : "f"(x)); return r;
}
__device__ __forceinline__ u64 packab(float a, float b) {
    u64 r; asm("mov.b64 %0, {%1, %2};" : "=l"(r) : "f"(a), "f"(b)); return r;
}
__device__ __forceinline__ void ffma2(u64& d, u64 a, u64 b) {
    asm("fma.rn.f32x2 %0, %1, %2, %0;" : "+l"(d) : "l"(a), "l"(b));
}
__device__ __forceinline__ float2 unpk(u64 v) {
    float2 f; asm("mov.b64 {%0, %1}, %2;" : "=f"(f.x), "=f"(f.y) : "l"(v)); return f;
}

// ---------------- adjacency build ----------------
__global__ void k_zero_deg() {
    int i = blockIdx.x * blockDim.x + threadIdx.x;
    if (i < Nc) g_node_deg[i] = 0;
}

__global__ void k_build_edges(const int* __restrict__ members,
                              const int* __restrict__ centers,
                              const int* __restrict__ offsets) {
    int e = blockIdx.x * blockDim.x + threadIdx.x;
    if (e >= Ec) return;
    int s = offsets[e], t = offsets[e + 1];
    int list[ESTRIDE];
    int cnt = 0;
    for (int m = s; m < t && cnt < ESTRIDE; m++) {
        int n = members[m];
        bool dup = false;
        for (int k = 0; k < cnt; k++) if (list[k] == n) { dup = true; break; }
        if (!dup) list[cnt++] = n;
    }
    {
        int c = centers[e];
        bool dup = false;
        for (int k = 0; k < cnt; k++) if (list[k] == c) { dup = true; break; }
        if (!dup && cnt < ESTRIDE) list[cnt++] = c;
    }
    g_edge_cnt[e] = cnt;
    for (int k = 0; k < cnt; k++) {
        int n = list[k];
        g_edge_nodes[e * ESTRIDE + k] = n;
        int pos = atomicAdd(&g_node_deg[n], 1);
        if (pos < MAXD) g_node_edges[n * MAXD + pos] = e;
    }
    for (int k = cnt; k < ESTRIDE; k++) g_edge_nodes[e * ESTRIDE + k] = Nc;  // dummy zero row
}

__global__ void k_sort_nodes() {
    int n = blockIdx.x * blockDim.x + threadIdx.x;
    if (n >= Nc) return;
    int d = g_node_deg[n];
    if (d > MAXD) d = MAXD;
    g_node_deg[n] = d;
    int* L = g_node_edges + n * MAXD;
    for (int i = 1; i < d; i++) {
        int key = L[i];
        int j = i - 1;
        while (j >= 0 && L[j] > key) { L[j + 1] = L[j]; j--; }
        L[j + 1] = key;
    }
    int d8 = (d + 7) & ~7;
    if (d8 > MAXD) d8 = MAXD;
    for (int i = d; i < d8; i++) L[i] = Ec;  // dummy: smem row 1000 zeroed
}

// ---------------- dynamic features: mean/std over T ----------------
__global__ void k_feat(const float* __restrict__ xraw) {
    int idx = blockIdx.x * blockDim.x + threadIdx.x;
    if (idx >= Bc * Nc * C_RAWc) return;
    int c = idx % C_RAWc;
    int n = (idx / C_RAWc) % Nc;
    int b = idx / (C_RAWc * Nc);
    float s1 = 0.f, s2 = 0.f;
    #pragma unroll
    for (int t = 0; t < Tc; t++) {
        float v = xraw[((b * Tc + t) * Nc + n) * C_RAWc + c];
        s1 += v; s2 += v * v;
    }
    float mean = s1 * (1.f / Tc);
    float var = s2 * (1.f / Tc) - mean * mean;
    if (var < 0.f) var = 0.f;
    g_feat[(b * Nc + n) * 16 + c] = mean;
    g_feat[(b * Nc + n) * 16 + C_RAWc + c] = sqrtf(var);
}

// ---------------- per-edge mean similarity (warp per (b,e)) ----------------
__global__ void k_sim(const int* __restrict__ members,
                      const int* __restrict__ centers,
                      const int* __restrict__ offsets) {
    int gid = blockIdx.x * (blockDim.x >> 5) + (threadIdx.x >> 5);
    if (gid >= Bc * Ec) return;
    int e = gid % Ec;
    int b = gid / Ec;
    int lane = threadIdx.x & 31;
    int s = offsets[e];
    int cntm = offsets[e + 1] - s;
    int cn = centers[e];
    const float4* cf4 = (const float4*)(g_feat + (b * Nc + cn) * 16);
    float4 c0 = cf4[0], c1 = cf4[1], c2 = cf4[2], c3 = cf4[3];
    float cn2 = c0.x*c0.x + c0.y*c0.y + c0.z*c0.z + c0.w*c0.w
              + c1.x*c1.x + c1.y*c1.y + c1.z*c1.z + c1.w*c1.w
              + c2.x*c2.x + c2.y*c2.y + c2.z*c2.z + c2.w*c2.w
              + c3.x*c3.x + c3.y*c3.y + c3.z*c3.z + c3.w*c3.w;
    float cnorm = sqrtf(cn2);
    float acc = 0.f;
    for (int m = lane; m < cntm; m += 32) {
        int n = members[s + m];
        const float4* mf4 = (const float4*)(g_feat + (b * Nc + n) * 16);
        float4 m0 = mf4[0], m1 = mf4[1], m2 = mf4[2], m3 = mf4[3];
        float dot = m0.x*c0.x + m0.y*c0.y + m0.z*c0.z + m0.w*c0.w
                  + m1.x*c1.x + m1.y*c1.y + m1.z*c1.z + m1.w*c1.w
                  + m2.x*c2.x + m2.y*c2.y + m2.z*c2.z + m2.w*c2.w
                  + m3.x*c3.x + m3.y*c3.y + m3.z*c3.z + m3.w*c3.w;
        float mn2 = m0.x*m0.x + m0.y*m0.y + m0.z*m0.z + m0.w*m0.w
                  + m1.x*m1.x + m1.y*m1.y + m1.z*m1.z + m1.w*m1.w
                  + m2.x*m2.x + m2.y*m2.y + m2.z*m2.z + m2.w*m2.w
                  + m3.x*m3.x + m3.y*m3.y + m3.z*m3.z + m3.w*m3.w;
        float sim = dot / (sqrtf(mn2) * cnorm + EPSc);
        acc += fminf(fmaxf(sim, 0.f), 1.f);
    }
    #pragma unroll
    for (int o = 16; o > 0; o >>= 1) acc += __shfl_xor_sync(FULLMASK, acc, o);
    if (lane == 0) {
        float count = (float)cntm;
        if (count < 1.f) count = 1.f;
        g_msum[b * Ec + e] = acc / count;
    }
}

// ---------------- per-batch min-max normalize -> Wd ----------------
__global__ void k_wd(const float* __restrict__ W) {
    int b = blockIdx.x;
    int tid = threadIdx.x;
    __shared__ float rmn[256], rmx[256];
    float mn = 1e30f, mx = -1e30f;
    for (int e = tid; e < Ec; e += 256) {
        float v = g_msum[b * Ec + e];
        mn = fminf(mn, v); mx = fmaxf(mx, v);
    }
    rmn[tid] = mn; rmx[tid] = mx;
    __syncthreads();
    for (int s = 128; s > 0; s >>= 1) {
        if (tid < s) {
            rmn[tid] = fminf(rmn[tid], rmn[tid + s]);
            rmx[tid] = fmaxf(rmx[tid], rmx[tid + s]);
        }
        __syncthreads();
    }
    mn = rmn[0]; mx = rmx[0];
    float inv = __fdividef(1.f, mx - mn + EPSc);
    for (int e = tid; e < Ec; e += 256) {
        float v = (g_msum[b * Ec + e] - mn) * inv;
        g_Wd[b * Ec + e] = W[e] * (1.f + LAMc * v);
    }
}

// ---------------- node degree weights -> dvi (warp per (b,n)) ----------------
__global__ void k_dvi() {
    int gid = blockIdx.x * (blockDim.x >> 5) + (threadIdx.x >> 5);
    if (gid >= Bc * Nc) return;
    int n = gid % Nc;
    int b = gid / Nc;
    int lane = threadIdx.x & 31;
    int d = g_node_deg[n];
    float s = 0.f;
    for (int i = lane; i < d; i += 32)
        s += g_Wd[b * Ec + g_node_edges[n * MAXD + i]];
    #pragma unroll
    for (int o = 16; o > 0; o >>= 1) s += __shfl_xor_sync(FULLMASK, s, o);
    if (lane == 0) g_dvi[gid] = rsqrtf(fmaxf(s, EPSc));
}

// ---------------- fold conv into input projection: ipwc = ipw@cw, ipbc = ipb@cw ----------------
__global__ void k_fold(const float* __restrict__ ipw, const float* __restrict__ ipb,
                       const float* __restrict__ cw) {
    int j = threadIdx.x & 31;
    int k = threadIdx.x >> 5;   // 512 threads: k in [0,16)
    float s = 0.f;
    #pragma unroll
    for (int f = 0; f < DMc; f++) s += ipw[k * DMc + f] * cw[f * HCc + j];
    g_ipwc[k * DMc + j] = s;
    if (threadIdx.x < 32) {
        float sb = 0.f;
        #pragma unroll
        for (int f = 0; f < DMc; f++) sb += ipb[f] * cw[f * HCc + j];
        g_ipbc[j] = sb;
    }
}

// ---------------- slice kernel: ys stage -> edge gather (regs) -> node gather -> g_hc ----------------
// one block per (b,t); 512 threads; smem reused between ys and edge features
__global__ __launch_bounds__(512) void k_slice(const float* __restrict__ x,
                                               const float* __restrict__ cbg) {
    extern __shared__ float xs[];            // (Nc+1)*32 floats, reused
    float* sipw = xs + (Nc + 1) * 32;        // 512
    float* sipb = sipw + 512;                // 32
    int bt = blockIdx.x;
    int b = bt / Tc;
    int t = bt % Tc;
    int lane = threadIdx.x & 31;
    int w = threadIdx.x >> 5;

    if (threadIdx.x < 512) sipw[threadIdx.x] = g_ipwc[threadIdx.x];
    if (threadIdx.x < 32) sipb[threadIdx.x] = g_ipbc[threadIdx.x];
    __syncthreads();

    // phase 1: ys = dvi * (x @ ipwc + ipbc)
    const float* xb = x + (size_t)bt * Nc * F_INc;
    float4* xs4 = (float4*)xs;
    for (int i = threadIdx.x; i < (Nc + 1) * 8; i += 512) {
        int n = i >> 3, q = (i & 7) * 4;
        float4 v = make_float4(0.f, 0.f, 0.f, 0.f);
        if (n < Nc) {
            const float* xr = xb + n * F_INc;
            float a0 = sipb[q], a1 = sipb[q + 1], a2 = sipb[q + 2], a3 = sipb[q + 3];
            #pragma unroll
            for (int k = 0; k < F_INc; k++) {
                float xv = xr[k];
                a0 += xv * sipw[k * 32 + q];
                a1 += xv * sipw[k * 32 + q + 1];
                a2 += xv * sipw[k * 32 + q + 2];
                a3 += xv * sipw[k * 32 + q + 3];
            }
            float d = g_dvi[b * Nc + n];
            v = make_float4(a0 * d, a1 * d, a2 * d, a3 * d);
        }
        xs4[i] = v;
    }
    __syncthreads();

    // phase 2: edge gather into registers (warp w owns edges [w*64, w*64+64))
    int e0 = w * 64;
    float u_reg[64];
    #pragma unroll
    for (int el = 0; el < 64; el++) {
        int e = e0 + el;
        float uv = 0.f;
        if (e < Ec) {
            const int4* ip = (const int4*)(g_edge_nodes + e * ESTRIDE);
            int4 a0 = ip[0], a1 = ip[1], a2 = ip[2], a3 = ip[3], a4 = ip[4], a5 = ip[5];
            float p0 = xs[a0.x * 32 + lane] + xs[a1.x * 32 + lane]
                     + xs[a2.x * 32 + lane] + xs[a3.x * 32 + lane]
                     + xs[a4.x * 32 + lane] + xs[a5.x * 32 + lane];
            float p1 = xs[a0.y * 32 + lane] + xs[a1.y * 32 + lane]
                     + xs[a2.y * 32 + lane] + xs[a3.y * 32 + lane]
                     + xs[a4.y * 32 + lane] + xs[a5.y * 32 + lane];
            float p2 = xs[a0.z * 32 + lane] + xs[a1.z * 32 + lane]
                     + xs[a2.z * 32 + lane] + xs[a3.z * 32 + lane]
                     + xs[a4.z * 32 + lane] + xs[a5.z * 32 + lane];
            float p3 = xs[a0.w * 32 + lane] + xs[a1.w * 32 + lane]
                     + xs[a2.w * 32 + lane] + xs[a3.w * 32 + lane]
                     + xs[a4.w * 32 + lane] + xs[a5.w * 32 + lane];
            float sc = __fdividef(g_Wd[b * Ec + e], (float)g_edge_cnt[e]);
            uv = ((p0 + p1) + (p2 + p3)) * sc;
        }
        u_reg[el] = uv;
    }
    __syncthreads();   // all reads of ys complete

    // phase 3: overwrite smem with edge features
    #pragma unroll
    for (int el = 0; el < 64; el++) {
        int e = e0 + el;
        if (e < Ec) xs[e * 32 + lane] = u_reg[el];
    }
    if (threadIdx.x < 32) xs[Nc * 32 + threadIdx.x] = 0.f;  // dummy row for node pad
    __syncthreads();

    // phase 4: node gather + silu -> g_hc  (conv already folded into ys)
    float cbv = cbg[lane];
    for (int n = w; n < Nc; n += 16) {
        int deg = g_node_deg[n];
        int d8 = (deg + 7) & ~7;
        const int* L = g_node_edges + n * MAXD;
        float p0 = 0.f, p1 = 0.f;
        for (int k = 0; k < d8; k += 8) {
            int4 a = *(const int4*)(L + k);
            int4 b2 = *(const int4*)(L + k + 4);
            p0 += xs[a.x * 32 + lane] + xs[a.z * 32 + lane]
                + xs[b2.x * 32 + lane] + xs[b2.z * 32 + lane];
            p1 += xs[a.y * 32 + lane] + xs[a.w * 32 + lane]
                + xs[b2.y * 32 + lane] + xs[b2.w * 32 + lane];
        }
        float z = (p0 + p1) * g_dvi[b * Nc + n] + cbv;
        g_hc[((size_t)(b * Nc + n) * Tc + t) * 32 + lane] = siluf(z);
    }
}

// ---------------- LSTM: smem f32x2 weights, 8 rows/warp, LDS.128 pairs + prefetch ----------------
__global__ __launch_bounds__(128) void k_lstm3(
    const float* __restrict__ wx, const float* __restrict__ wh,
    const float* __restrict__ lb,
    const float* __restrict__ hw1, const float* __restrict__ hb1,
    const float* __restrict__ hw2, const float* __restrict__ hb2,
    float* __restrict__ out, int Pout) {
    extern __shared__ __align__(16) char smr[];
    u64*   swp  = (u64*)smr;             // 4096: {w01,w23} pairs, index (i*32+lane)*2
    u64*   hb   = swp + 4096;            // 4 warps * 8 rows * 64
    float* hw1S = (float*)(hb + 2048);   // 1024
    float* hb1S = hw1S + 1024;           // 32
    float* hw2S = hb1S + 32;             // 384
    float* hb2S = hw2S + 384;            // 16

    int tid = threadIdx.x, lane = tid & 31, w = tid >> 5;
    int rb = blockIdx.x * 32 + w * 8;

    for (int idx = tid; idx < 2048; idx += 128) {
        int i = idx >> 5, l = idx & 31;
        const float* src = (i < 32) ? (wx + i * 128) : (wh + (i - 32) * 128);
        swp[idx * 2]     = packab(src[l], src[32 + l]);
        swp[idx * 2 + 1] = packab(src[64 + l], src[96 + l]);
    }
    for (int i = tid; i < 1024; i += 128) hw1S[i] = hw1[i];
    for (int i = tid; i < 384; i += 128) hw2S[i] = hw2[i];
    if (tid < 32) hb1S[tid] = hb1[tid];
    if (tid < PREDc) hb2S[tid] = hb2[tid];

    u64 bz01 = packab(lb[lane], lb[32 + lane]);
    u64 bz23 = packab(lb[64 + lane], lb[96 + lane]);
    __syncthreads();

    u64* hbw = hb + w * 512;
    const ulonglong2* swp2 = (const ulonglong2*)swp;

    float hcv[8], h[8], c[8];
    #pragma unroll
    for (int r = 0; r < 8; r++) {
        h[r] = 0.f; c[r] = 0.f;
        hcv[r] = g_hc[((size_t)(rb + r) * Tc) * 32 + lane];
    }

    for (int t = 0; t < Tc; t++) {
        #pragma unroll
        for (int r = 0; r < 8; r++) {
            hbw[r * 64 + lane] = pack11(hcv[r]);
            hbw[r * 64 + 32 + lane] = pack11(h[r]);
        }
        float hcn[8];
        if (t + 1 < Tc) {
            #pragma unroll
            for (int r = 0; r < 8; r++)
                hcn[r] = g_hc[((size_t)(rb + r) * Tc + t + 1) * 32 + lane];
        }
        __syncwarp();
        u64 z01[8], z23[8];
        #pragma unroll
        for (int r = 0; r < 8; r++) { z01[r] = bz01; z23[r] = bz23; }
        #pragma unroll 8
        for (int i = 0; i < 64; i += 2) {
            ulonglong2 wA = swp2[i * 32 + lane];
            ulonglong2 wB = swp2[(i + 1) * 32 + lane];
            #pragma unroll
            for (int r = 0; r < 8; r++) {
                ulonglong2 hp = *(const ulonglong2*)&hbw[r * 64 + i];
                ffma2(z01[r], hp.x, wA.x);
                ffma2(z23[r], hp.x, wA.y);
                ffma2(z01[r], hp.y, wB.x);
                ffma2(z23[r], hp.y, wB.y);
            }
        }
        #pragma unroll
        for (int r = 0; r < 8; r++) {
            float2 zif = unpk(z01[r]);
            float2 zgo = unpk(z23[r]);
            float ig = sigmf(zif.x);
            float fg = sigmf(zif.y);
            float gg = tanhf_(zgo.x);
            float og = sigmf(zgo.y);
            c[r] = fg * c[r] + ig * gg;
            h[r] = og * tanhf_(c[r]);
            hcv[r] = hcn[r];
        }
        __syncwarp();
    }

    // head: y = silu(h @ hw1 + hb1) @ hw2 + hb2
    #pragma unroll
    for (int r = 0; r < 8; r++) {
        int row = rb + r;
        int b = row / Nc;
        int n = row % Nc;
        float a = hb1S[lane];
        #pragma unroll 8
        for (int i = 0; i < 32; i++) {
            float hi = __shfl_sync(FULLMASK, h[r], i);
            a += hi * hw1S[i * 32 + lane];
        }
        float y1 = siluf(a);
        float o = (lane < PREDc) ? hb2S[lane] : 0.f;
        #pragma unroll 8
        for (int j = 0; j < 32; j++) {
            float yj = __shfl_sync(FULLMASK, y1, j);
            if (lane < PREDc) o += yj * hw2S[j * PREDc + lane];
        }
        if (lane < Pout) out[((size_t)b * Pout + lane) * Nc + n] = o;
    }
}

// ---------------- launch ----------------
extern "C" void kernel_launch(void* const* d_in, const int* in_sizes, int n_in,
                              void* d_out, int out_size) {
    const float* x       = (const float*)d_in[0];
    const float* xraw    = (const float*)d_in[1];
    const float* W       = (const float*)d_in[3];
    const int*   members = (const int*)d_in[4];
    const int*   centers = (const int*)d_in[5];
    const int*   offsets = (const int*)d_in[6];
    const float* ipw     = (const float*)d_in[7];
    const float* ipb     = (const float*)d_in[8];
    const float* cw      = (const float*)d_in[9];
    const float* cb      = (const float*)d_in[10];
    const float* wx      = (const float*)d_in[11];
    const float* wh      = (const float*)d_in[12];
    const float* lb      = (const float*)d_in[13];
    const float* hw1     = (const float*)d_in[14];
    const float* hb1     = (const float*)d_in[15];
    const float* hw2     = (const float*)d_in[16];
    const float* hb2     = (const float*)d_in[17];
    float* out = (float*)d_out;
    int Pout = out_size / (Bc * Nc);

    int smem_slice = ((Nc + 1) * 32 + 512 + 32) * sizeof(float);          // 130304
    int smem_lstm  = 6144 * sizeof(u64) + 1456 * sizeof(float);           // 54976
    cudaFuncSetAttribute(k_slice, cudaFuncAttributeMaxDynamicSharedMemorySize, smem_slice);
    cudaFuncSetAttribute(k_lstm3, cudaFuncAttributeMaxDynamicSharedMemorySize, smem_lstm);

    k_zero_deg<<<4, 256>>>();
    k_build_edges<<<4, 256>>>(members, centers, offsets);
    k_sort_nodes<<<4, 256>>>();
    k_feat<<<(Bc * Nc * C_RAWc + 255) / 256, 256>>>(xraw);
    k_sim<<<(Bc * Ec + 7) / 8, 256>>>(members, centers, offsets);
    k_wd<<<Bc, 256>>>(W);
    k_dvi<<<(Bc * Nc + 7) / 8, 256>>>();
    k_fold<<<1, 512>>>(ipw, ipb, cw);
    k_slice<<<Bc * Tc, 512, smem_slice>>>(x, cb);
    k_lstm3<<<Bc * Nc / 32, 128, smem_lstm>>>(wx, wh, lb, hw1, hb1, hw2, hb2, out, Pout);
}